// round 6
// baseline (speedup 1.0000x reference)
#include <cuda_runtime.h>

#define DIM 8192
typedef unsigned long long u64;

// ---- packed f32x2 helpers (SASS FFMA2/FMUL2 path, PTX-only) ----
__device__ __forceinline__ float2 f2fma(float2 a, float2 b, float2 c) {
    u64 r, au = *(u64*)&a, bu = *(u64*)&b, cu = *(u64*)&c;
    asm("fma.rn.f32x2 %0,%1,%2,%3;" : "=l"(r) : "l"(au), "l"(bu), "l"(cu));
    return *(float2*)&r;
}
__device__ __forceinline__ float2 f2mul(float2 a, float2 b) {
    u64 r, au = *(u64*)&a, bu = *(u64*)&b;
    asm("mul.rn.f32x2 %0,%1,%2;" : "=l"(r) : "l"(au), "l"(bu));
    return *(float2*)&r;
}
__device__ __forceinline__ float2 f2add(float2 a, float2 b) {
    u64 r, au = *(u64*)&a, bu = *(u64*)&b;
    asm("add.rn.f32x2 %0,%1,%2;" : "=l"(r) : "l"(au), "l"(bu));
    return *(float2*)&r;
}

// XOR swizzle: conflict-free smem for ALL structured layouts below
// (incl. the warp-local transpose whose phase-varying bits are 4 and 9-12).
__device__ __forceinline__ int phys(int i) {
    return i ^ ((i >> 4) & 15) ^ ((i >> 9) & 15);
}

// Phase tables (shared by all batch rows):
//   g_t0[i] = layer-0 phi diagonal (applied to the real input)
//   g_t1a   = B0(i)*A1(M0(i)), rearranged for a coalesced gather in layout C'.
// All trailing diagonals are unit-modulus under |amp|^2 -> dropped.
__device__ float2 g_t0[DIM];
__device__ float2 g_t1a[DIM];

#define ROWS1_INIT {8191,8190,8188,8184,8176,8160,8128,8064,7936,7680,7168,6144,4095}

__global__ void qc_setup(const float* __restrict__ w) {
    const int i = blockIdx.x * blockDim.x + threadIdx.x;   // 0..8191
    const int ROWS1[13] = ROWS1_INIT;
    float a0 = 0.f, b0 = 0.f;
#pragma unroll
    for (int q = 0; q < 13; q++) {
        const float sgn = ((i >> (12 - q)) & 1) ? 0.5f : -0.5f;
        a0 += sgn * w[q*3 + 0];       // layer-0 phi
        b0 += sgn * w[q*3 + 2];       // layer-0 omega
    }
    int j = 0;
#pragma unroll
    for (int t = 0; t < 13; t++) j |= (__popc(ROWS1[t] & i) & 1) << t;
    float a1 = 0.f;
#pragma unroll
    for (int q = 0; q < 13; q++) {
        const float sgn = ((j >> (12 - q)) & 1) ? 0.5f : -0.5f;
        a1 += sgn * w[39 + q*3 + 0];  // layer-1 phi at M0-permuted index
    }
    float c, s;
    sincosf(a0, &s, &c);      g_t0[i] = make_float2(c, s);
    sincosf(b0 + a1, &s, &c); g_t1a[((i & 511) << 4) | (i >> 9)] = make_float2(c, s);
}

// Plain single-bit real RY rotation on register-bit BQ.
template<int BQ>
__device__ __forceinline__ void rotY(float2 (&re)[16], float2 (&im)[16],
                                     float2 c, float2 s, float2 ns) {
#pragma unroll
    for (int k0 = 0; k0 < 16; k0++) {
        if (k0 & (1 << BQ)) continue;
        const int k1 = k0 | (1 << BQ);
        const float2 r0 = re[k0], r1 = re[k1], i0 = im[k0], i1 = im[k1];
        re[k0] = f2fma(c, r0, f2mul(ns, r1));
        re[k1] = f2fma(s, r0, f2mul(c,  r1));
        im[k0] = f2fma(c, i0, f2mul(ns, i1));
        im[k1] = f2fma(s, i0, f2mul(c,  i1));
    }
}

__global__ void __launch_bounds__(512, 1)
qc_kernel(const float* __restrict__ x, const float* __restrict__ w,
          float* __restrict__ out)
{
    extern __shared__ float4 st[];                 // 8192 x (re-pack, im-pack) = 128 KB
    __shared__ float2 gc[26], gs[26], gns[26];     // RY coeffs, duplicated packed
    __shared__ float2 red[16];

    const int t    = threadIdx.x;
    const int b    = blockIdx.x;                   // batch rows 2b, 2b+1
    const int lane = t & 31;
    const int warp = t >> 5;
    const int cbase = warp << 9;

    if (t < 26) {
        const int l = t / 13, q = t - l * 13;
        const float th = w[l*39 + q*3 + 1];
        float s, c; sincosf(0.5f * th, &s, &c);
        gc[t]  = make_float2( c,  c);
        gs[t]  = make_float2( s,  s);
        gns[t] = make_float2(-s, -s);
    }

    // ---- load two rows (layout A1: i = (t<<4)|k), reduce sum-of-squares ----
    float2 re[16], im[16];
    const float4* xp0 = reinterpret_cast<const float4*>(x + (size_t)(2*b)   * DIM + (t << 4));
    const float4* xp1 = reinterpret_cast<const float4*>(x + (size_t)(2*b+1) * DIM + (t << 4));
    float2 ss = make_float2(0.f, 0.f);
#pragma unroll
    for (int k4 = 0; k4 < 4; k4++) {
        const float4 v0 = xp0[k4];
        const float4 v1 = xp1[k4];
        re[k4*4+0] = make_float2(v0.x, v1.x);
        re[k4*4+1] = make_float2(v0.y, v1.y);
        re[k4*4+2] = make_float2(v0.z, v1.z);
        re[k4*4+3] = make_float2(v0.w, v1.w);
    }
#pragma unroll
    for (int k = 0; k < 16; k++) ss = f2fma(re[k], re[k], ss);
#pragma unroll
    for (int o = 16; o > 0; o >>= 1) {
        u64 sv = *(u64*)&ss;
        u64 ov = __shfl_xor_sync(0xffffffffu, sv, o);
        ss = f2add(ss, *(float2*)&ov);
    }
    if (lane == 0) red[warp] = ss;
    __syncthreads();                                             // BAR 1
    float2 tot = make_float2(0.f, 0.f);
#pragma unroll
    for (int r = 0; r < 16; r++) tot = f2add(tot, red[r]);
    const float2 inv = make_float2(rsqrtf(tot.x), rsqrtf(tot.y));

    // ---- A0: layer-0 phi phase on the real normalized input ----
    const float4* t0p = reinterpret_cast<const float4*>(g_t0) + (t << 3);
#pragma unroll
    for (int kk = 0; kk < 8; kk++) {
        const float4 cs = __ldg(&t0p[kk]);
        const int k0 = 2*kk, k1 = 2*kk + 1;
        float2 xs = f2mul(re[k0], inv);
        re[k0] = f2mul(xs, make_float2(cs.x, cs.x));
        im[k0] = f2mul(xs, make_float2(cs.y, cs.y));
        xs = f2mul(re[k1], inv);
        re[k1] = f2mul(xs, make_float2(cs.z, cs.z));
        im[k1] = f2mul(xs, make_float2(cs.w, cs.w));
    }

    // ==== LAYER 0 ====
    // pass A1: reg bits = i bits 0-3 (qubits 12..9)
    rotY<0>(re, im, gc[12], gs[12], gns[12]);
    rotY<1>(re, im, gc[11], gs[11], gns[11]);
    rotY<2>(re, im, gc[10], gs[10], gns[10]);
    rotY<3>(re, im, gc[ 9], gs[ 9], gns[ 9]);

    // warp-local exchange A1 -> A2 (reg bits = i bits 4-7)
    const int a2base = cbase | ((lane & 16) << 4) | (lane & 15);
#pragma unroll
    for (int k = 0; k < 16; k++)
        st[phys(cbase | (lane << 4) | k)] = make_float4(re[k].x, re[k].y, im[k].x, im[k].y);
    __syncwarp();
#pragma unroll
    for (int k = 0; k < 16; k++) {
        const float4 v = st[phys(a2base | (k << 4))];
        re[k] = make_float2(v.x, v.y); im[k] = make_float2(v.z, v.w);
    }
    rotY<0>(re, im, gc[8], gs[8], gns[8]);
    rotY<1>(re, im, gc[7], gs[7], gns[7]);
    rotY<2>(re, im, gc[6], gs[6], gns[6]);
    rotY<3>(re, im, gc[5], gs[5], gns[5]);

    // store A2 layout, then block exchange with the bit-8 gate (qubit 4)
    // FUSED into the load: read own + partner (pt^256) and combine.
#pragma unroll
    for (int k = 0; k < 16; k++)
        st[phys(a2base | (k << 4))] = make_float4(re[k].x, re[k].y, im[k].x, im[k].y);
    __syncthreads();                                             // BAR 2
    const int pt  = (lane << 4) | warp;
    const int ppt = ((lane ^ 16) << 4) | warp;
    {
        const float2 cg   = gc[4];
        const float2 sSel = (lane & 16) ? gs[4] : gns[4];
#pragma unroll
        for (int k = 0; k < 16; k++) {
            const float4 v  = st[phys((k << 9) | pt)];
            const float4 vp = st[phys((k << 9) | ppt)];
            re[k] = f2fma(cg, make_float2(v.x, v.y), f2mul(sSel, make_float2(vp.x, vp.y)));
            im[k] = f2fma(cg, make_float2(v.z, v.w), f2mul(sSel, make_float2(vp.z, vp.w)));
        }
    }
    // pass C': reg bits = i bits 9-12 (qubits 3..0)
    rotY<0>(re, im, gc[3], gs[3], gns[3]);
    rotY<1>(re, im, gc[2], gs[2], gns[2]);
    rotY<2>(re, im, gc[1], gs[1], gns[1]);
    rotY<3>(re, im, gc[0], gs[0], gns[0]);

    // ==== D01 diagonal (layer-0 omega + layer-1 phi @ M0(i)) ====
    const float4* t1p = reinterpret_cast<const float4*>(g_t1a) + (pt << 3);
#pragma unroll
    for (int kk = 0; kk < 8; kk++) {
        const float4 cs = __ldg(&t1p[kk]);
        {
            const int k0 = 2*kk;
            const float2 cd = make_float2(cs.x, cs.x);
            const float2 sd = make_float2(cs.y, cs.y);
            const float2 nd = make_float2(-cs.y, -cs.y);
            const float2 tr = f2fma(cd, re[k0], f2mul(nd, im[k0]));
            const float2 ti = f2fma(sd, re[k0], f2mul(cd, im[k0]));
            re[k0] = tr; im[k0] = ti;
        }
        {
            const int k1 = 2*kk + 1;
            const float2 cd = make_float2(cs.z, cs.z);
            const float2 sd = make_float2(cs.w, cs.w);
            const float2 nd = make_float2(-cs.w, -cs.w);
            const float2 tr = f2fma(cd, re[k1], f2mul(nd, im[k1]));
            const float2 ti = f2fma(sd, re[k1], f2mul(cd, im[k1]));
            re[k1] = tr; im[k1] = ti;
        }
    }

    // ==== LAYER 1: the 4 observable-relevant gates, conjugated by M0 ====
    // d12 = {11,12} (k-mask 12), orient = parity(i & 4095) : gate 13 (qubit 0)
    {
        const int Pt = __popc(pt) & 1;
        const float2 c = gc[13];
#pragma unroll
        for (int k0 = 0; k0 < 8; k0++) {
            const int k1 = k0 ^ 12;
            const int o = Pt ^ (__popc(k0 & 7) & 1);
            const float2 sa = o ? gs[13] : gns[13];
            const float2 sb = o ? gns[13] : gs[13];
            const float2 ar = re[k0], ai = im[k0], br = re[k1], bi = im[k1];
            re[k0] = f2fma(c, ar, f2mul(sa, br));
            im[k0] = f2fma(c, ai, f2mul(sa, bi));
            re[k1] = f2fma(c, br, f2mul(sb, ar));
            im[k1] = f2fma(c, bi, f2mul(sb, ai));
        }
    }
    // d10 = {9,10} (k-mask 3), orient = parity(k & 14) : gate 15 (qubit 2)
    {
        const float2 c = gc[15];
#pragma unroll
        for (int k0 = 0; k0 < 16; k0++) {
            if ((k0 & 3) > 1) continue;
            const int k1 = k0 ^ 3;
            const int o = __popc(k0 & 14) & 1;
            const float2 sa = o ? gs[15] : gns[15];
            const float2 sb = o ? gns[15] : gs[15];
            const float2 ar = re[k0], ai = im[k0], br = re[k1], bi = im[k1];
            re[k0] = f2fma(c, ar, f2mul(sa, br));
            im[k0] = f2fma(c, ai, f2mul(sa, bi));
            re[k1] = f2fma(c, br, f2mul(sb, ar));
            im[k1] = f2fma(c, bi, f2mul(sb, ai));
        }
    }

    // ==== warp-local transpose (barrier-free): bring i bits 5-8 into regs ====
    // Store back to the exact slots this warp read in the C' exchange
    // (slots s with s&15 == warp are warp-private from here on).
#pragma unroll
    for (int k = 0; k < 16; k++)
        st[phys((k << 9) | pt)] = make_float4(re[k].x, re[k].y, im[k].x, im[k].y);
    __syncwarp();
    // New layout: reg k = i bits 5-8; lane bits 0-3 = i bits 9-12, lane bit 4 = i bit 4
#pragma unroll
    for (int k = 0; k < 16; k++) {
        const int s = ((lane & 15) << 9) | (k << 5) | ((lane >> 4) << 4) | warp;
        const float4 v = st[phys(s)];
        re[k] = make_float2(v.x, v.y); im[k] = make_float2(v.z, v.w);
    }

    // d8 = {7,8} (now k-mask 12), orient = parity(lane & 15) : gate 17 (qubit 4)
    {
        const float2 c = gc[17];
        const int o8 = __popc(lane & 15) & 1;
        const float2 sa = o8 ? gs[17] : gns[17];
        const float2 sb = o8 ? gns[17] : gs[17];
#pragma unroll
        for (int k0 = 0; k0 < 8; k0++) {
            const int k1 = k0 ^ 12;
            const float2 ar = re[k0], ai = im[k0], br = re[k1], bi = im[k1];
            re[k0] = f2fma(c, ar, f2mul(sa, br));
            im[k0] = f2fma(c, ai, f2mul(sa, bi));
            re[k1] = f2fma(c, br, f2mul(sb, ar));
            im[k1] = f2fma(c, bi, f2mul(sb, ai));
        }
    }
    // d6 = {5,6} (now k-mask 3), orient = parity(k&12) ^ parity(lane&15) : gate 19 (qubit 6)
    {
        const float2 c = gc[19];
        const int oL = __popc(lane & 15) & 1;
#pragma unroll
        for (int k0 = 0; k0 < 16; k0++) {
            if ((k0 & 3) > 1) continue;
            const int k1 = k0 ^ 3;
            const int o = oL ^ (__popc(k0 & 12) & 1);
            const float2 sa = o ? gs[19] : gns[19];
            const float2 sb = o ? gns[19] : gs[19];
            const float2 ar = re[k0], ai = im[k0], br = re[k1], bi = im[k1];
            re[k0] = f2fma(c, ar, f2mul(sa, br));
            im[k0] = f2fma(c, ai, f2mul(sa, bi));
            re[k1] = f2fma(c, br, f2mul(sb, ar));
            im[k1] = f2fma(c, bi, f2mul(sb, ai));
        }
    }

    // ==== measurement: sign = parity(i & 4927) in the transposed layout ====
    // lane mask: bits {4(i4), 0(i9), 3(i12)} -> 25; k mask: bits {0(i5), 3(i8)} -> 9; + warp parity
    const float2 mn1 = make_float2(-1.f, -1.f);
    const int sgt = (__popc(lane & 25) + __popc(warp)) & 1;
    float2 acc = make_float2(0.f, 0.f);
#pragma unroll
    for (int k = 0; k < 16; k++) {
        const float2 p = f2fma(re[k], re[k], f2mul(im[k], im[k]));
        if (__popc(k & 9) & 1) acc = f2fma(p, mn1, acc);
        else                   acc = f2add(acc, p);
    }
    if (sgt) acc = f2mul(acc, mn1);
#pragma unroll
    for (int o = 16; o > 0; o >>= 1) {
        u64 av = *(u64*)&acc;
        u64 ov = __shfl_xor_sync(0xffffffffu, av, o);
        acc = f2add(acc, *(float2*)&ov);
    }
    if (lane == 0) red[warp] = acc;
    __syncthreads();                                             // BAR 3
    if (t == 0) {
        float2 tt = make_float2(0.f, 0.f);
#pragma unroll
        for (int r = 0; r < 16; r++) tt = f2add(tt, red[r]);
        out[2*b]   = tt.x;
        out[2*b+1] = tt.y;
    }
}

extern "C" void kernel_launch(void* const* d_in, const int* in_sizes, int n_in,
                              void* d_out, int out_size)
{
    const float* x = (const float*)d_in[0];
    const float* w = (const float*)d_in[1];
    float* out = (float*)d_out;
    const int B2 = (in_sizes[0] / DIM) / 2;        // 2 batch rows per CTA

    qc_setup<<<DIM / 256, 256>>>(w);

    const size_t shmem = DIM * sizeof(float4);     // 128 KB
    cudaFuncSetAttribute(qc_kernel, cudaFuncAttributeMaxDynamicSharedMemorySize,
                         (int)shmem);
    qc_kernel<<<B2, 512, shmem>>>(x, w, out);
}

// round 8
// speedup vs baseline: 1.0727x; 1.0727x over previous
#include <cuda_runtime.h>

#define DIM 8192
typedef unsigned long long u64;

// ---- packed f32x2 helpers (SASS FFMA2/FMUL2 path, PTX-only) ----
__device__ __forceinline__ float2 f2fma(float2 a, float2 b, float2 c) {
    u64 r, au = *(u64*)&a, bu = *(u64*)&b, cu = *(u64*)&c;
    asm("fma.rn.f32x2 %0,%1,%2,%3;" : "=l"(r) : "l"(au), "l"(bu), "l"(cu));
    return *(float2*)&r;
}
__device__ __forceinline__ float2 f2mul(float2 a, float2 b) {
    u64 r, au = *(u64*)&a, bu = *(u64*)&b;
    asm("mul.rn.f32x2 %0,%1,%2;" : "=l"(r) : "l"(au), "l"(bu));
    return *(float2*)&r;
}
__device__ __forceinline__ float2 f2add(float2 a, float2 b) {
    u64 r, au = *(u64*)&a, bu = *(u64*)&b;
    asm("add.rn.f32x2 %0,%1,%2;" : "=l"(r) : "l"(au), "l"(bu));
    return *(float2*)&r;
}

// XOR swizzle: conflict-free smem for all structured layouts used below.
__device__ __forceinline__ int phys(int i) {
    return i ^ ((i >> 4) & 15);
}

// Phase tables (shared by all batch rows):
//   g_t0[i] = layer-0 phi diagonal (applied to the real input)
//   g_t1a   = B0(i)*A1(M0(i)), rearranged for a coalesced gather in layout C'.
// All trailing diagonals are unit-modulus under |amp|^2 -> dropped.
__device__ float2 g_t0[DIM];
__device__ float2 g_t1a[DIM];

#define ROWS1_INIT {8191,8190,8188,8184,8176,8160,8128,8064,7936,7680,7168,6144,4095}

__global__ void qc_setup(const float* __restrict__ w) {
    const int i = blockIdx.x * blockDim.x + threadIdx.x;   // 0..8191
    const int ROWS1[13] = ROWS1_INIT;
    float a0 = 0.f, b0 = 0.f;
#pragma unroll
    for (int q = 0; q < 13; q++) {
        const float sgn = ((i >> (12 - q)) & 1) ? 0.5f : -0.5f;
        a0 += sgn * w[q*3 + 0];       // layer-0 phi
        b0 += sgn * w[q*3 + 2];       // layer-0 omega
    }
    int j = 0;
#pragma unroll
    for (int t = 0; t < 13; t++) j |= (__popc(ROWS1[t] & i) & 1) << t;
    float a1 = 0.f;
#pragma unroll
    for (int q = 0; q < 13; q++) {
        const float sgn = ((j >> (12 - q)) & 1) ? 0.5f : -0.5f;
        a1 += sgn * w[39 + q*3 + 0];  // layer-1 phi at M0-permuted index
    }
    float c, s;
    sincosf(a0, &s, &c);      g_t0[i] = make_float2(c, s);
    sincosf(b0 + a1, &s, &c); g_t1a[((i & 511) << 4) | (i >> 9)] = make_float2(c, s);
}

// Plain single-bit real RY rotation on register-bit BQ.
template<int BQ>
__device__ __forceinline__ void rotY(float2 (&re)[16], float2 (&im)[16],
                                     float2 c, float2 s, float2 ns) {
#pragma unroll
    for (int k0 = 0; k0 < 16; k0++) {
        if (k0 & (1 << BQ)) continue;
        const int k1 = k0 | (1 << BQ);
        const float2 r0 = re[k0], r1 = re[k1], i0 = im[k0], i1 = im[k1];
        re[k0] = f2fma(c, r0, f2mul(ns, r1));
        re[k1] = f2fma(s, r0, f2mul(c,  r1));
        im[k0] = f2fma(c, i0, f2mul(ns, i1));
        im[k1] = f2fma(s, i0, f2mul(c,  i1));
    }
}

__global__ void __launch_bounds__(512, 1)
qc_kernel(const float* __restrict__ x, const float* __restrict__ w,
          float* __restrict__ out)
{
    extern __shared__ float4 st[];                 // 8192 x (re-pack, im-pack) = 128 KB
    __shared__ float2 gc[26], gs[26], gns[26];     // RY coeffs, duplicated packed
    __shared__ float2 red[16], red2[16];

    const int t    = threadIdx.x;
    const int b    = blockIdx.x;                   // batch rows 2b, 2b+1
    const int lane = t & 31;
    const int warp = t >> 5;
    const int cbase = warp << 9;

    // Gate coefficients into smem (threads 0-25). The barrier making these
    // visible is BELOW, hidden under the global-load latency of x.
    if (t < 26) {
        const int l = t / 13, q = t - l * 13;
        const float th = w[l*39 + q*3 + 1];
        float s, c; sincosf(0.5f * th, &s, &c);
        gc[t]  = make_float2( c,  c);
        gs[t]  = make_float2( s,  s);
        gns[t] = make_float2(-s, -s);
    }

    // ---- load two rows (layout A1: i = (t<<4)|k). NO normalization here:
    // the circuit is linear, so we carry ss = ||x||^2 and divide at the end.
    float2 re[16], im[16];
    const float4* xp0 = reinterpret_cast<const float4*>(x + (size_t)(2*b)   * DIM + (t << 4));
    const float4* xp1 = reinterpret_cast<const float4*>(x + (size_t)(2*b+1) * DIM + (t << 4));
    float2 ss = make_float2(0.f, 0.f);
#pragma unroll
    for (int k4 = 0; k4 < 4; k4++) {
        const float4 v0 = xp0[k4];
        const float4 v1 = xp1[k4];
        re[k4*4+0] = make_float2(v0.x, v1.x);
        re[k4*4+1] = make_float2(v0.y, v1.y);
        re[k4*4+2] = make_float2(v0.z, v1.z);
        re[k4*4+3] = make_float2(v0.w, v1.w);
    }
#pragma unroll
    for (int k = 0; k < 16; k++) ss = f2fma(re[k], re[k], ss);

    __syncthreads();   // BAR 1: gate coeffs visible (hidden under x-load latency)

    // ---- A0: layer-0 phi phase on the (unnormalized) real input ----
    const float4* t0p = reinterpret_cast<const float4*>(g_t0) + (t << 3);
#pragma unroll
    for (int kk = 0; kk < 8; kk++) {
        const float4 cs = __ldg(&t0p[kk]);
        const int k0 = 2*kk, k1 = 2*kk + 1;
        const float2 x0 = re[k0];
        re[k0] = f2mul(x0, make_float2(cs.x, cs.x));
        im[k0] = f2mul(x0, make_float2(cs.y, cs.y));
        const float2 x1 = re[k1];
        re[k1] = f2mul(x1, make_float2(cs.z, cs.z));
        im[k1] = f2mul(x1, make_float2(cs.w, cs.w));
    }

    // ==== LAYER 0 ====
    // pass A1: reg bits = i bits 0-3 (qubits 12..9)
    rotY<0>(re, im, gc[12], gs[12], gns[12]);
    rotY<1>(re, im, gc[11], gs[11], gns[11]);
    rotY<2>(re, im, gc[10], gs[10], gns[10]);
    rotY<3>(re, im, gc[ 9], gs[ 9], gns[ 9]);

    // warp-local exchange A1 -> A2 (reg bits = i bits 4-7)
    const int a2base = cbase | ((lane & 16) << 4) | (lane & 15);
#pragma unroll
    for (int k = 0; k < 16; k++)
        st[phys(cbase | (lane << 4) | k)] = make_float4(re[k].x, re[k].y, im[k].x, im[k].y);
    __syncwarp();
#pragma unroll
    for (int k = 0; k < 16; k++) {
        const float4 v = st[phys(a2base | (k << 4))];
        re[k] = make_float2(v.x, v.y); im[k] = make_float2(v.z, v.w);
    }
    rotY<0>(re, im, gc[8], gs[8], gns[8]);
    rotY<1>(re, im, gc[7], gs[7], gns[7]);
    rotY<2>(re, im, gc[6], gs[6], gns[6]);
    rotY<3>(re, im, gc[5], gs[5], gns[5]);

    // store A2 layout (pre-bit-8-gate), then block exchange with the bit-8
    // gate (qubit 4) FUSED into the load: read own + partner and combine.
#pragma unroll
    for (int k = 0; k < 16; k++)
        st[phys(a2base | (k << 4))] = make_float4(re[k].x, re[k].y, im[k].x, im[k].y);
    __syncthreads();                                             // BAR 2
    const int pt  = (lane << 4) | warp;
    const int ppt = ((lane ^ 16) << 4) | warp;
    {
        const float2 cg   = gc[4];
        const float2 sSel = (lane & 16) ? gs[4] : gns[4];
#pragma unroll
        for (int k = 0; k < 16; k++) {
            const float4 v  = st[phys((k << 9) | pt)];
            const float4 vp = st[phys((k << 9) | ppt)];
            re[k] = f2fma(cg, make_float2(v.x, v.y), f2mul(sSel, make_float2(vp.x, vp.y)));
            im[k] = f2fma(cg, make_float2(v.z, v.w), f2mul(sSel, make_float2(vp.z, vp.w)));
        }
    }
    // pass C': reg bits = i bits 9-12 (qubits 3..0)
    rotY<0>(re, im, gc[3], gs[3], gns[3]);
    rotY<1>(re, im, gc[2], gs[2], gns[2]);
    rotY<2>(re, im, gc[1], gs[1], gns[1]);
    rotY<3>(re, im, gc[0], gs[0], gns[0]);

    // ==== D01 diagonal (layer-0 omega + layer-1 phi @ M0(i)) ====
    const float4* t1p = reinterpret_cast<const float4*>(g_t1a) + (pt << 3);
#pragma unroll
    for (int kk = 0; kk < 8; kk++) {
        const float4 cs = __ldg(&t1p[kk]);
        {
            const int k0 = 2*kk;
            const float2 cd = make_float2(cs.x, cs.x);
            const float2 sd = make_float2(cs.y, cs.y);
            const float2 nd = make_float2(-cs.y, -cs.y);
            const float2 tr = f2fma(cd, re[k0], f2mul(nd, im[k0]));
            const float2 ti = f2fma(sd, re[k0], f2mul(cd, im[k0]));
            re[k0] = tr; im[k0] = ti;
        }
        {
            const int k1 = 2*kk + 1;
            const float2 cd = make_float2(cs.z, cs.z);
            const float2 sd = make_float2(cs.w, cs.w);
            const float2 nd = make_float2(-cs.w, -cs.w);
            const float2 tr = f2fma(cd, re[k1], f2mul(nd, im[k1]));
            const float2 ti = f2fma(sd, re[k1], f2mul(cd, im[k1]));
            re[k1] = tr; im[k1] = ti;
        }
    }

    // ==== LAYER 1: the 4 observable-relevant gates, conjugated by M0 ====
    // d12 = {11,12} (k-mask 12), orient = parity(i & 4095) : gate 13 (qubit 0)
    {
        const int Pt = __popc(pt) & 1;
        const float2 c = gc[13];
#pragma unroll
        for (int k0 = 0; k0 < 8; k0++) {
            const int k1 = k0 ^ 12;
            const int o = Pt ^ (__popc(k0 & 7) & 1);
            const float2 sa = o ? gs[13] : gns[13];
            const float2 sb = o ? gns[13] : gs[13];
            const float2 ar = re[k0], ai = im[k0], br = re[k1], bi = im[k1];
            re[k0] = f2fma(c, ar, f2mul(sa, br));
            im[k0] = f2fma(c, ai, f2mul(sa, bi));
            re[k1] = f2fma(c, br, f2mul(sb, ar));
            im[k1] = f2fma(c, bi, f2mul(sb, ai));
        }
    }
    // d10 = {9,10} (k-mask 3), orient = parity(k & 14) : gate 15 (qubit 2)
    {
        const float2 c = gc[15];
#pragma unroll
        for (int k0 = 0; k0 < 16; k0++) {
            if ((k0 & 3) > 1) continue;
            const int k1 = k0 ^ 3;
            const int o = __popc(k0 & 14) & 1;
            const float2 sa = o ? gs[15] : gns[15];
            const float2 sb = o ? gns[15] : gs[15];
            const float2 ar = re[k0], ai = im[k0], br = re[k1], bi = im[k1];
            re[k0] = f2fma(c, ar, f2mul(sa, br));
            im[k0] = f2fma(c, ai, f2mul(sa, bi));
            re[k1] = f2fma(c, br, f2mul(sb, ar));
            im[k1] = f2fma(c, bi, f2mul(sb, ai));
        }
    }
    // d8 = {7,8} (lane-mask 24, shfl), orient = lane bit4 ^ parity(k) : gate 17 (qubit 4)
    {
        const float2 c = gc[17];
        const int oL = (lane >> 4) & 1;
        const float2 sEv = oL ? gs[17] : gns[17];
        const float2 sOd = oL ? gns[17] : gs[17];
#pragma unroll
        for (int k = 0; k < 16; k++) {
            const u64 pr = __shfl_xor_sync(0xffffffffu, *(u64*)&re[k], 24);
            const u64 pi = __shfl_xor_sync(0xffffffffu, *(u64*)&im[k], 24);
            const float2 sc = (__popc(k) & 1) ? sOd : sEv;
            re[k] = f2fma(c, re[k], f2mul(sc, *(const float2*)&pr));
            im[k] = f2fma(c, im[k], f2mul(sc, *(const float2*)&pi));
        }
    }
    // d6 = {5,6} (lane-mask 6, shfl), orient = parity(lane&28) ^ parity(k) : gate 19 (qubit 6)
    {
        const float2 c = gc[19];
        const int oL = __popc(lane & 28) & 1;
        const float2 sEv = oL ? gs[19] : gns[19];
        const float2 sOd = oL ? gns[19] : gs[19];
#pragma unroll
        for (int k = 0; k < 16; k++) {
            const u64 pr = __shfl_xor_sync(0xffffffffu, *(u64*)&re[k], 6);
            const u64 pi = __shfl_xor_sync(0xffffffffu, *(u64*)&im[k], 6);
            const float2 sc = (__popc(k) & 1) ? sOd : sEv;
            re[k] = f2fma(c, re[k], f2mul(sc, *(const float2*)&pr));
            im[k] = f2fma(c, im[k], f2mul(sc, *(const float2*)&pi));
        }
    }

    // ==== measurement: sign = parity(i & 4927) in i-space ====
    // thread part: lane-mask 19 ^ warp parity; k part: k-mask 9
    const float2 mn1 = make_float2(-1.f, -1.f);
    const int sgt = (__popc(lane & 19) + __popc(warp)) & 1;
    float2 acc = make_float2(0.f, 0.f);
#pragma unroll
    for (int k = 0; k < 16; k++) {
        const float2 p = f2fma(re[k], re[k], f2mul(im[k], im[k]));
        if (__popc(k & 9) & 1) acc = f2fma(p, mn1, acc);
        else                   acc = f2add(acc, p);
    }
    if (sgt) acc = f2mul(acc, mn1);
    // joint reduction of the signed sum and ||x||^2
#pragma unroll
    for (int o = 16; o > 0; o >>= 1) {
        u64 av = *(u64*)&acc;
        u64 ov = __shfl_xor_sync(0xffffffffu, av, o);
        acc = f2add(acc, *(float2*)&ov);
        u64 sv = *(u64*)&ss;
        u64 so = __shfl_xor_sync(0xffffffffu, sv, o);
        ss = f2add(ss, *(float2*)&so);
    }
    if (lane == 0) { red[warp] = acc; red2[warp] = ss; }
    __syncthreads();                                             // BAR 3
    if (t == 0) {
        float2 ta = make_float2(0.f, 0.f);
        float2 ts = make_float2(0.f, 0.f);
#pragma unroll
        for (int r = 0; r < 16; r++) { ta = f2add(ta, red[r]); ts = f2add(ts, red2[r]); }
        out[2*b]   = ta.x / ts.x;
        out[2*b+1] = ta.y / ts.y;
    }
}

extern "C" void kernel_launch(void* const* d_in, const int* in_sizes, int n_in,
                              void* d_out, int out_size)
{
    const float* x = (const float*)d_in[0];
    const float* w = (const float*)d_in[1];
    float* out = (float*)d_out;
    const int B2 = (in_sizes[0] / DIM) / 2;        // 2 batch rows per CTA

    qc_setup<<<DIM / 256, 256>>>(w);

    const size_t shmem = DIM * sizeof(float4);     // 128 KB
    cudaFuncSetAttribute(qc_kernel, cudaFuncAttributeMaxDynamicSharedMemorySize,
                         (int)shmem);
    qc_kernel<<<B2, 512, shmem>>>(x, w, out);
}